// round 17
// baseline (speedup 1.0000x reference)
#include <cuda_runtime.h>
#include <cuda_fp16.h>

#define N_NODES 50000
#define N_EDGES 1600000
#define NBATCH  12500        // total 128-edge CTA-batches
#define GRID    592          // 148 SMs x 4 CTAs -> exactly one wave

// Per-node precomputed readout vectors (one 128B line per node).
__device__ __align__(128) float g_prep[N_NODES * 32];
// L1 k8 frags: 8 frags x 32 lanes (uint = half2)
__device__ __align__(16) unsigned g_wfrags1[256];
// L2/L3/L4 k16 frags: 72 frags x 32 lanes (uint2)
__device__ __align__(16) uint2 g_wfrags2[2304];

// ---- SMEM layout (4-byte word offsets) ----
#define CS_STR  132          // csm row stride; 264c+g mod 32 = 8c+g -> conflict-free
#define WF1_OFF 0            // 256 words
#define WF2_OFF 256          // 4608 words
#define CS_OFF  4864         // 16 rows x 132 = 2112
#define RS_OFF  6976         // 128 receiver ids
#define HX_OFF  7104         // 4 pairs x 1280 words (exchange, aliases praw staging)
#define HX_PSTR 1280         // words per pair
#define HX_RSTR 40           // exchange row stride: (40c+g) mod 32 = 8c+g -> conflict-free
#define SMEM_WORDS (HX_OFF + 4 * HX_PSTR)
#define SMEM_BYTES (SMEM_WORDS * 4)   // 48896 B -> 4 CTAs fit (195.6KB < 228KB)

// frag bases inside wf2 (units of frags = 32 uint2)
#define FB_L2 0
#define FB_L3 32
#define FB_L4 64

__device__ __forceinline__ unsigned h2bits(__half2 h) { return *(unsigned*)&h; }

// silu via HW tanh, fully fp16x2: silu(x) = h + h*tanh(h), h = x/2.
__device__ __forceinline__ unsigned silu_h2(float x0, float x1) {
    __half2 h = __floats2half2_rn(x0, x1);
    __half2 hh = __hmul2(h, __floats2half2_rn(0.5f, 0.5f));
    unsigned t;
    asm("tanh.approx.f16x2 %0, %1;" : "=r"(t) : "r"(h2bits(hh)));
    __half2 r = __hfma2(hh, *(__half2*)&t, hh);
    return h2bits(r);
}

__device__ __forceinline__ void mma_f16(float* d, unsigned a0, unsigned a1,
                                        unsigned a2, unsigned a3,
                                        unsigned b0, unsigned b1) {
    asm volatile(
        "mma.sync.aligned.m16n8k16.row.col.f32.f16.f16.f32 "
        "{%0,%1,%2,%3}, {%4,%5,%6,%7}, {%8,%9}, {%0,%1,%2,%3};"
        : "+f"(d[0]), "+f"(d[1]), "+f"(d[2]), "+f"(d[3])
        : "r"(a0), "r"(a1), "r"(a2), "r"(a3), "r"(b0), "r"(b1));
}

__device__ __forceinline__ void mma_f16_k8(float* d, unsigned a0, unsigned a1, unsigned b0) {
    asm volatile(
        "mma.sync.aligned.m16n8k8.row.col.f32.f16.f16.f32 "
        "{%0,%1,%2,%3}, {%4,%5}, {%6}, {%0,%1,%2,%3};"
        : "+f"(d[0]), "+f"(d[1]), "+f"(d[2]), "+f"(d[3])
        : "r"(a0), "r"(a1), "r"(b0));
}

__device__ __forceinline__ void red1(float* a, float v) {
    asm volatile("red.global.add.f32 [%0], %1;" :: "l"(a), "f"(v) : "memory");
}

// ============================================================================
// Setup kernel: weight frag packing (low blocks) + per-node prep + out zero.
// ============================================================================
__global__ void __launch_bounds__(256)
setup_kernel(const float* __restrict__ nf,
             const float* __restrict__ W0,
             const float* __restrict__ W1,
             const float* __restrict__ w1, const float* __restrict__ w2,
             const float* __restrict__ w3, const float* __restrict__ w4,
             float* __restrict__ out)
{
    const int tid = threadIdx.x;
    const float s8 = 0.3535533905932738f, s64 = 0.125f;

    int idx = blockIdx.x * 256 + tid;
    if (idx < 256) {
        int f = idx >> 5, lane = idx & 31;
        int c = lane & 3, g = lane >> 2;
        int n = f * 8 + g;
        __half2 p = __floats2half2_rn(w1[(2*c) * 64 + n] * s8,
                                      w1[(2*c + 1) * 64 + n] * s8);
        g_wfrags1[idx] = h2bits(p);
    } else if (idx < 2560) {
        int t = idx - 256;
        int f = t >> 5, lane = t & 31;
        int c = lane & 3, g = lane >> 2;
        const float* w; int ncols, NT, fl;
        if (f < 32)      { w = w2; ncols = 64; NT = 8; fl = f; }
        else if (f < 64) { w = w3; ncols = 64; NT = 8; fl = f - 32; }
        else             { w = w4; ncols = 16; NT = 2; fl = f - 64; }
        int kt = fl / NT, nt = fl - kt * NT;
        int n = nt * 8 + g, kb = kt * 16 + 2 * c;
        __half2 x = __floats2half2_rn(w[kb * ncols + n] * s64,
                                      w[(kb + 1) * ncols + n] * s64);
        __half2 y = __floats2half2_rn(w[(kb + 8) * ncols + n] * s64,
                                      w[(kb + 9) * ncols + n] * s64);
        g_wfrags2[t] = make_uint2(h2bits(x), h2bits(y));
    }

    __shared__ float sW0[512], sW1[512];
    for (int i = tid; i < 512; i += 256) { sW0[i] = W0[i]; sW1[i] = W1[i]; }
    __syncthreads();

    const int warp = tid >> 5;
    const int lane = tid & 31;
    const int n = blockIdx.x * 8 + warp;
    if (n >= N_NODES) return;

    const float* nrow = nf + (size_t)n * 256;
    const int v1 = lane, v2 = lane + 32;
    float x1 = nrow[v1], x2 = nrow[v2];
    float y1[3], y2[3];
    #pragma unroll
    for (int k = 0; k < 3; k++) {
        y1[k] = nrow[64 + v1 * 3 + k];
        y2[k] = nrow[64 + v2 * 3 + k];
    }

    float P[32];
    #pragma unroll
    for (int u = 0; u < 8; u++)
        P[u] = fmaf(sW0[u * 64 + v1], x1, sW0[u * 64 + v2] * x2);
    #pragma unroll
    for (int u = 0; u < 8; u++) {
        float wa = sW1[u * 64 + v1], wb = sW1[u * 64 + v2];
        #pragma unroll
        for (int k = 0; k < 3; k++)
            P[8 + u * 3 + k] = fmaf(wa, y1[k], wb * y2[k]);
    }

    #pragma unroll
    for (int off = 16; off; off >>= 1) {
        #pragma unroll
        for (int j = 0; j < 32; j++)
            P[j] += __shfl_xor_sync(0xffffffffu, P[j], off);
    }

    if (lane == 0) {
        const float c0 = 0.03125f;
        const float c1 = 0.03125f * 0.5773502691896258f;
        float* dst = g_prep + (size_t)n * 32;
        #pragma unroll
        for (int j = 0; j < 8; j++)  dst[j] = P[j] * c0;
        #pragma unroll
        for (int j = 8; j < 32; j++) dst[j] = P[j] * c1;
        out[n] = 0.f;
    }
}

// ============================================================================
// Edge kernel: warp-pair N-split. Pair (2p,2p+1) shares 32 edges; each warp
// computes 32 of the 64 outputs. Activations exchanged via per-pair SMEM.
// ============================================================================
__global__ void __launch_bounds__(256, 4)
edge_kernel(const float* __restrict__ ef,
            const float* __restrict__ ea,
            const float* __restrict__ qi,
            const int*   __restrict__ eidx,
            float* __restrict__ out)
{
    extern __shared__ float smem[];
    unsigned* wf1 = (unsigned*)smem;
    uint2*    wf2 = (uint2*)(smem + WF2_OFF);
    float*    csm = smem + CS_OFF;
    int*      rsm = (int*)(smem + RS_OFF);

    const int tid  = threadIdx.x;
    const int lane = tid & 31;
    const int warp = tid >> 5;
    const int p    = warp >> 1;          // pair id 0..3
    const int nw   = warp & 1;           // n-half within pair
    const int half = lane & 1;
    const int cm   = warp * 16 + (lane >> 1);  // gather edge column (CTA-local)
    const int c    = lane & 3;
    const int g    = lane >> 2;
    const unsigned FULL = 0xffffffffu;

    unsigned* hxp  = (unsigned*)(smem + HX_OFF + p * HX_PSTR);
    float*    praw = smem + HX_OFF + p * HX_PSTR + nw * 576;   // aliases hx

    #define PBAR() asm volatile("bar.sync %0, 64;" :: "r"(p + 1) : "memory")

    // Weight frags -> SMEM (block-cooperative).
    {
        const float4* s1 = (const float4*)g_wfrags1;
        float4* d1 = (float4*)smem;
        if (tid < 64) d1[tid] = s1[tid];
        const float4* s2 = (const float4*)g_wfrags2;
        float4* d2 = (float4*)(smem + WF2_OFF);
        #pragma unroll
        for (int i = 0; i < 4; i++) d2[tid + i * 256] = s2[tid + i * 256];
        if (tid < 128) d2[tid + 1024] = s2[tid + 1024];
    }
    __syncthreads();

    float acc[8][4];
    unsigned sa[2][4], sb[2][4];   // own silu'd half: [mt][nt'] edge g / g+8
    #define ZACC(N) { _Pragma("unroll") for (int i = 0; i < N; i++) { \
        acc[i][0]=0.f; acc[i][1]=0.f; acc[i][2]=0.f; acc[i][3]=0.f; } }

    // k16 layer body: A from own regs (kt in own half) or partner via hx.
    #define LAYER64(FB) { \
        _Pragma("unroll") \
        for (int kt = 0; kt < 4; kt++) { \
            unsigned A0[2], A1[2], A2[2], A3[2]; \
            if ((kt >> 1) == nw) { \
                int n0 = 2 * (kt & 1); \
                _Pragma("unroll") \
                for (int mt = 0; mt < 2; mt++) { \
                    A0[mt] = sa[mt][n0];   A1[mt] = sb[mt][n0]; \
                    A2[mt] = sa[mt][n0+1]; A3[mt] = sb[mt][n0+1]; \
                } \
            } else { \
                _Pragma("unroll") \
                for (int mt = 0; mt < 2; mt++) { \
                    int b0 = (8*kt + c) * HX_RSTR + 16*mt + g; \
                    int b1 = (8*kt + 4 + c) * HX_RSTR + 16*mt + g; \
                    A0[mt] = hxp[b0]; A1[mt] = hxp[b0 + 8]; \
                    A2[mt] = hxp[b1]; A3[mt] = hxp[b1 + 8]; \
                } \
            } \
            _Pragma("unroll") \
            for (int nt = 0; nt < 4; nt++) { \
                uint2 b = wf2[((FB) + kt * 8 + 4 * nw + nt) * 32 + lane]; \
                mma_f16(acc[nt],     A0[0], A1[0], A2[0], A3[0], b.x, b.y); \
                mma_f16(acc[4 + nt], A0[1], A1[1], A2[1], A3[1], b.x, b.y); \
            } \
        } }

    // silu + keep own half in regs + publish to hx.
    #define SILU_STORE() { \
        _Pragma("unroll") \
        for (int mt = 0; mt < 2; mt++) { \
            _Pragma("unroll") \
            for (int nt = 0; nt < 4; nt++) { \
                unsigned lo = silu_h2(acc[mt*4+nt][0], acc[mt*4+nt][1]); \
                unsigned hi = silu_h2(acc[mt*4+nt][2], acc[mt*4+nt][3]); \
                sa[mt][nt] = lo; sb[mt][nt] = hi; \
                int row = (16*nw + 4*nt + c) * HX_RSTR + 16*mt + g; \
                hxp[row] = lo; hxp[row + 8] = hi; \
            } \
        } }

    // Persistent grid-stride over 128-edge CTA-batches.
    #pragma unroll 1
    for (int bi = blockIdx.x; bi < NBATCH; bi += GRID) {
        PBAR();   // prev batch's hx reads / csm tail reads complete pair-wide

        const int me  = bi * 128 + cm;
        const int ebp = bi * 128 + p * 32;

        // ---- Gather (each warp: its 16 of the pair's 32 edges) ----
        const int s_ = eidx[me];
        const int r_ = eidx[N_EDGES + me];
        float4 at = *(const float4*)(ea + (size_t)me * 4);
        float4 q0 = *(const float4*)(qi + (size_t)s_ * 8);
        float4 q1 = *(const float4*)(qi + (size_t)s_ * 8 + 4);
        // L1 A inputs for BOTH m-tiles (pair's 32 edges)
        float2 f00 = *(const float2*)(ef + (size_t)(ebp + g)      * 8 + 2 * c);
        float2 f01 = *(const float2*)(ef + (size_t)(ebp + 8 + g)  * 8 + 2 * c);
        float2 f10 = *(const float2*)(ef + (size_t)(ebp + 16 + g) * 8 + 2 * c);
        float2 f11 = *(const float2*)(ef + (size_t)(ebp + 24 + g) * 8 + 2 * c);

        // Coalesced prep staging (own 16 edges).
        #pragma unroll
        for (int t = 0; t < 4; t++) {
            int E  = t * 4 + (lane >> 3);
            int rE = __shfl_sync(FULL, r_, 2 * E);
            float4 v = *(const float4*)(g_prep + (size_t)rE * 32 + (lane & 7) * 4);
            *(float4*)(praw + E * 36 + (lane & 7) * 4) = v;
        }
        if (half == 0) rsm[cm] = r_;
        __syncwarp();

        // Contract into csm[16][edge].
        const float* pw = praw + (lane >> 1) * 36;
        float q[8] = {q0.x, q0.y, q0.z, q0.w, q1.x, q1.y, q1.z, q1.w};
        if (half == 0) {
            float4 Aa = *(const float4*)pw;
            float4 Ab = *(const float4*)(pw + 4);
            float A0v[8] = {Aa.x, Aa.y, Aa.z, Aa.w, Ab.x, Ab.y, Ab.z, Ab.w};
            #pragma unroll
            for (int u = 0; u < 8; u++) csm[u * CS_STR + cm] = (q[u] * at.x) * A0v[u];
        } else {
            float A1v[24];
            #pragma unroll
            for (int i = 0; i < 6; i++) {
                float4 v = *(const float4*)(pw + 8 + 4 * i);
                A1v[4*i] = v.x; A1v[4*i+1] = v.y; A1v[4*i+2] = v.z; A1v[4*i+3] = v.w;
            }
            #pragma unroll
            for (int u = 0; u < 8; u++) {
                float bs = at.y * A1v[3*u];
                bs = fmaf(at.z, A1v[3*u + 1], bs);
                bs = fmaf(at.w, A1v[3*u + 2], bs);
                csm[(8 + u) * CS_STR + cm] = q[u] * bs;
            }
        }
        PBAR();   // praw reads done pair-wide; csm/rsm visible

        // ---- Layer 1: 8 -> 64 (k8), own NT=4 ----
        unsigned a00 = h2bits(__floats2half2_rn(f00.x, f00.y));
        unsigned a01 = h2bits(__floats2half2_rn(f01.x, f01.y));
        unsigned a10 = h2bits(__floats2half2_rn(f10.x, f10.y));
        unsigned a11 = h2bits(__floats2half2_rn(f11.x, f11.y));
        ZACC(8);
        #pragma unroll
        for (int nt = 0; nt < 4; nt++) {
            unsigned b = wf1[(4 * nw + nt) * 32 + lane];
            mma_f16_k8(acc[nt],     a00, a01, b);
            mma_f16_k8(acc[4 + nt], a10, a11, b);
        }
        SILU_STORE();
        PBAR();   // hx halves visible

        // ---- Layer 2 ----
        ZACC(8);
        LAYER64(FB_L2);
        PBAR();   // partner done reading hx (WAR)
        SILU_STORE();
        PBAR();   // hx visible

        // ---- Layer 3 ----
        ZACC(8);
        LAYER64(FB_L3);
        PBAR();   // WAR
        SILU_STORE();
        PBAR();   // visible

        // ---- Layer 4: own nt = nw ----
        float ac2[2][4];
        #pragma unroll
        for (int i = 0; i < 2; i++) { ac2[i][0]=0.f; ac2[i][1]=0.f; ac2[i][2]=0.f; ac2[i][3]=0.f; }
        #pragma unroll
        for (int kt = 0; kt < 4; kt++) {
            unsigned A0[2], A1[2], A2[2], A3[2];
            if ((kt >> 1) == nw) {
                int n0 = 2 * (kt & 1);
                #pragma unroll
                for (int mt = 0; mt < 2; mt++) {
                    A0[mt] = sa[mt][n0];   A1[mt] = sb[mt][n0];
                    A2[mt] = sa[mt][n0+1]; A3[mt] = sb[mt][n0+1];
                }
            } else {
                #pragma unroll
                for (int mt = 0; mt < 2; mt++) {
                    int b0 = (8*kt + c) * HX_RSTR + 16*mt + g;
                    int b1 = (8*kt + 4 + c) * HX_RSTR + 16*mt + g;
                    A0[mt] = hxp[b0]; A1[mt] = hxp[b0 + 8];
                    A2[mt] = hxp[b1]; A3[mt] = hxp[b1 + 8];
                }
            }
            uint2 b = wf2[(FB_L4 + kt * 2 + nw) * 32 + lane];
            mma_f16(ac2[0], A0[0], A1[0], A2[0], A3[0], b.x, b.y);
            mma_f16(ac2[1], A0[1], A1[1], A2[1], A3[1], b.x, b.y);
        }

        // ---- Tail: partial dot over own 8 tp rows, atomic per edge ----
        const float* c0p = csm + (8 * nw + 2 * c) * CS_STR;
        const float* c1p = c0p + CS_STR;
        #pragma unroll
        for (int mt = 0; mt < 2; mt++) {
            int E = p * 32 + 16 * mt + g;
            float sA = ac2[mt][0] * c0p[E]     + ac2[mt][1] * c1p[E];
            float sB = ac2[mt][2] * c0p[E + 8] + ac2[mt][3] * c1p[E + 8];
            sA += __shfl_xor_sync(FULL, sA, 1);
            sA += __shfl_xor_sync(FULL, sA, 2);
            sB += __shfl_xor_sync(FULL, sB, 1);
            sB += __shfl_xor_sync(FULL, sB, 2);
            if (c == 0) {
                red1(out + rsm[E],     sA);
                red1(out + rsm[E + 8], sB);
            }
        }
    }
    #undef PBAR
    #undef LAYER64
    #undef SILU_STORE
}

extern "C" void kernel_launch(void* const* d_in, const int* in_sizes, int n_in,
                              void* d_out, int out_size)
{
    const float* node_feats      = (const float*)d_in[0];
    const float* charges_induced = (const float*)d_in[2];
    const float* edge_feats      = (const float*)d_in[3];
    const float* edge_attrs      = (const float*)d_in[4];
    const float* mlp_w1          = (const float*)d_in[6];
    const float* mlp_w2          = (const float*)d_in[7];
    const float* mlp_w3          = (const float*)d_in[8];
    const float* mlp_w4          = (const float*)d_in[9];
    const float* W0              = (const float*)d_in[10];
    const float* W1              = (const float*)d_in[11];
    const int*   eidx            = (const int*)d_in[12];
    float* out = (float*)d_out;

    setup_kernel<<<(N_NODES + 7) / 8, 256>>>(node_feats, W0, W1,
                                             mlp_w1, mlp_w2, mlp_w3, mlp_w4, out);

    cudaFuncSetAttribute(edge_kernel, cudaFuncAttributeMaxDynamicSharedMemorySize, SMEM_BYTES);
    edge_kernel<<<GRID, 256, SMEM_BYTES>>>(
        edge_feats, edge_attrs, charges_induced, eidx, out);
}